// round 2
// baseline (speedup 1.0000x reference)
#include <cuda_runtime.h>

// ProteinContactMapDecoder: out[i,j,k] = sum_d X[i+1,d]*X[j+1,d]*Wp[d,k] + b[k]
// (diff term is antisymmetric and cancels under the reference's symmetrization;
//  prod term is already symmetric). Output shape (510,510,2), fp32.
//
// Inputs (metadata order): prev_result (1,512,1280) f32; W (2560,2) f32; b (2,) f32.

#define DD 1280
#define LL 512
#define NN 510          // output rows/cols (1..510 of X)
#define TILE 32
#define BK 32
#define NB 16           // ceil(510/32)
#define NBLK (NB * (NB + 1) / 2)   // 136 upper-triangular tile pairs

__global__ __launch_bounds__(256, 1)
void contact_gram_kernel(const float* __restrict__ X,
                         const float* __restrict__ W,
                         const float* __restrict__ b,
                         float* __restrict__ out)
{
    // Map linear block id -> upper-triangular tile (bi <= bj)
    int t = blockIdx.x;
    int bi = 0;
    {
        int rem = t;
        #pragma unroll
        for (int r = 0; r < NB; r++) {
            int rowlen = NB - r;
            if (rem < rowlen) { bi = r; break; }
            rem -= rowlen;
        }
        t = rem;          // column offset within row
    }
    int bj = bi + t;

    const int tx = threadIdx.x;       // 0..15
    const int ty = threadIdx.y;       // 0..15
    const int tid = ty * 16 + tx;     // 0..255

    // +2 pad keeps 8B alignment for float2 reads and avoids bank conflicts
    __shared__ float sXi [TILE][BK + 2];
    __shared__ float sYj0[TILE][BK + 2];   // X_j * Wp[:,0]
    __shared__ float sYj1[TILE][BK + 2];   // X_j * Wp[:,1]

    float acc000 = 0.f, acc001 = 0.f, acc010 = 0.f, acc011 = 0.f;
    float acc100 = 0.f, acc101 = 0.f, acc110 = 0.f, acc111 = 0.f;

    const int cload = tid & 31;        // d-offset this thread loads (constant across s)
    const int rload0 = tid >> 5;       // row 0..7; rows r = rload0 + 8*s

    for (int kt = 0; kt < DD / BK; kt++) {
        const int d0 = kt * BK;
        const float w0 = W[(d0 + cload) * 2 + 0];
        const float w1 = W[(d0 + cload) * 2 + 1];

        #pragma unroll
        for (int s = 0; s < 4; s++) {
            int r = rload0 + s * 8;
            int gi = bi * TILE + r;                 // output-row index
            float vi = 0.f;
            if (gi < NN) vi = X[(gi + 1) * DD + d0 + cload];
            sXi[r][cload] = vi;

            int gj = bj * TILE + r;
            float vj = 0.f;
            if (gj < NN) vj = X[(gj + 1) * DD + d0 + cload];
            sYj0[r][cload] = vj * w0;
            sYj1[r][cload] = vj * w1;
        }
        __syncthreads();

        #pragma unroll
        for (int kk = 0; kk < BK; kk += 2) {
            float2 xi0 = *(const float2*)&sXi [ty     ][kk];
            float2 xi1 = *(const float2*)&sXi [ty + 16][kk];
            float2 a0  = *(const float2*)&sYj0[tx     ][kk];
            float2 c0  = *(const float2*)&sYj1[tx     ][kk];
            float2 a1  = *(const float2*)&sYj0[tx + 16][kk];
            float2 c1  = *(const float2*)&sYj1[tx + 16][kk];

            acc000 += xi0.x * a0.x;  acc000 += xi0.y * a0.y;
            acc001 += xi0.x * c0.x;  acc001 += xi0.y * c0.y;
            acc010 += xi0.x * a1.x;  acc010 += xi0.y * a1.y;
            acc011 += xi0.x * c1.x;  acc011 += xi0.y * c1.y;
            acc100 += xi1.x * a0.x;  acc100 += xi1.y * a0.y;
            acc101 += xi1.x * c0.x;  acc101 += xi1.y * c0.y;
            acc110 += xi1.x * a1.x;  acc110 += xi1.y * a1.y;
            acc111 += xi1.x * c1.x;  acc111 += xi1.y * c1.y;
        }
        __syncthreads();
    }

    const float bb0 = b[0];
    const float bb1 = b[1];
    float2* out2 = (float2*)out;

    const int i0 = bi * TILE + ty;
    const int i1 = i0 + 16;
    const int j0 = bj * TILE + tx;
    const int j1 = j0 + 16;

    // store value at [i,j] and its mirror [j,i] (symmetric output)
    #define STORE_PAIR(I, J, A0, A1)                                  \
        if ((I) < NN && (J) < NN) {                                   \
            float2 v = make_float2((A0) + bb0, (A1) + bb1);           \
            out2[(I) * NN + (J)] = v;                                 \
            out2[(J) * NN + (I)] = v;                                 \
        }

    STORE_PAIR(i0, j0, acc000, acc001);
    STORE_PAIR(i0, j1, acc010, acc011);
    STORE_PAIR(i1, j0, acc100, acc101);
    STORE_PAIR(i1, j1, acc110, acc111);
    #undef STORE_PAIR
}

extern "C" void kernel_launch(void* const* d_in, const int* in_sizes, int n_in,
                              void* d_out, int out_size)
{
    const float* X = (const float*)d_in[0];   // prev_result (1,512,1280)
    const float* W = (const float*)d_in[1];   // (2560,2)
    const float* b = (const float*)d_in[2];   // (2,)
    float* out = (float*)d_out;               // (510,510,2)

    dim3 block(16, 16);
    contact_gram_kernel<<<NBLK, block>>>(X, W, b, out);
}

// round 3
// speedup vs baseline: 1.0965x; 1.0965x over previous
#include <cuda_runtime.h>

// out[i,j,k] = sum_d X[i+1,d]*X[j+1,d]*Wp[d,k] + b[k]   (510,510,2) fp32
// diff term is antisymmetric -> cancels under symmetrization; prod term symmetric.
// 32x32 output tiles, upper-triangular (136 blocks), mirrored stores.
// 512 threads = 2 k-split groups of 256; per-group named barriers + double buffering.

#define DD   1280
#define NN   510
#define TILE 32
#define BK   32
#define PAD  34                 // 32 + 2: float2-aligned, conflict-free
#define NB   16
#define NBLK (NB * (NB + 1) / 2)   // 136
#define GROUPS 2
#define TPG    256
#define THREADS (GROUPS * TPG)
#define KT_PER_G (DD / (BK * GROUPS))   // 20
#define ARR (TILE * PAD)        // floats per smem array

// dynamic smem: [ sW: DD*2 ][ GROUPS x 2 bufs x 3 arrays x ARR ]
#define SMEM_FLOATS (DD * 2 + GROUPS * 2 * 3 * ARR)

extern __shared__ float smem_dyn[];

__global__ __launch_bounds__(THREADS, 1)
void contact_gram_kernel(const float* __restrict__ X,
                         const float* __restrict__ W,
                         const float* __restrict__ b,
                         float* __restrict__ out)
{
    const int tid = threadIdx.x;
    const int g   = tid >> 8;         // k-group 0/1
    const int lt  = tid & 255;        // lane within group
    const int tx  = lt & 15;
    const int ty  = lt >> 4;

    // linear block id -> upper-triangular (bi, bj), bi <= bj
    int t = blockIdx.x, bi = 0;
    #pragma unroll
    for (int r = 0; r < NB; r++) { int len = NB - r; if (t < len) { bi = r; break; } t -= len; }
    const int bj = bi + t;

    float* sW   = smem_dyn;                 // DD*2 floats
    float* sTop = smem_dyn + DD * 2;

    // buffer base for (group g, buffer bf): sTop + (g*2+bf)*3*ARR
    // arrays: +0 = Xi, +ARR = Yj0 (Xj*w0), +2*ARR = Yj1 (Xj*w1)

    // stage W into smem (whole block)
    for (int i = tid; i < DD * 2; i += THREADS) sW[i] = W[i];

    // tile-load mapping: thread lt -> row rl (0..31), cols cl..cl+3
    const int rl = lt >> 3;
    const int cl = (lt & 7) * 4;
    const int gi = bi * TILE + rl;
    const int gj = bj * TILE + rl;
    const int d_base = g * (DD / GROUPS);   // 0 or 640

    const float4 zero4 = make_float4(0.f, 0.f, 0.f, 0.f);

    // prologue: LDG tile 0
    float4 pxi = (gi < NN) ? *(const float4*)&X[(gi + 1) * DD + d_base + cl] : zero4;
    float4 pxj = (gj < NN) ? *(const float4*)&X[(gj + 1) * DD + d_base + cl] : zero4;

    __syncthreads();   // sW visible to everyone

    // store tile to buffer bf for k-tile starting at d0 (uses pxi/pxj + sW)
    #define STORE_TILE(bf, d0)                                                 \
    {                                                                          \
        float* base = sTop + ((g * 2 + (bf)) * 3) * ARR;                       \
        float2 w0 = *(const float2*)&sW[((d0) + cl + 0) * 2];                  \
        float2 w1 = *(const float2*)&sW[((d0) + cl + 1) * 2];                  \
        float2 w2 = *(const float2*)&sW[((d0) + cl + 2) * 2];                  \
        float2 w3 = *(const float2*)&sW[((d0) + cl + 3) * 2];                  \
        int o = rl * PAD + cl;                                                 \
        *(float2*)&base[o]     = make_float2(pxi.x, pxi.y);                    \
        *(float2*)&base[o + 2] = make_float2(pxi.z, pxi.w);                    \
        *(float2*)&base[ARR + o]     = make_float2(pxj.x * w0.x, pxj.y * w1.x);\
        *(float2*)&base[ARR + o + 2] = make_float2(pxj.z * w2.x, pxj.w * w3.x);\
        *(float2*)&base[2*ARR + o]     = make_float2(pxj.x * w0.y, pxj.y * w1.y);\
        *(float2*)&base[2*ARR + o + 2] = make_float2(pxj.z * w2.y, pxj.w * w3.y);\
    }

    #define GBAR() asm volatile("bar.sync %0, %1;" :: "r"(g + 1), "n"(TPG))

    STORE_TILE(0, d_base);
    GBAR();

    float a000 = 0.f, a001 = 0.f, a010 = 0.f, a011 = 0.f;
    float a100 = 0.f, a101 = 0.f, a110 = 0.f, a111 = 0.f;

    for (int kt = 0; kt < KT_PER_G; kt++) {
        const int cur = kt & 1;

        // prefetch next k-tile into registers (overlaps with compute below)
        if (kt + 1 < KT_PER_G) {
            const int d0 = d_base + (kt + 1) * BK;
            pxi = (gi < NN) ? *(const float4*)&X[(gi + 1) * DD + d0 + cl] : zero4;
            pxj = (gj < NN) ? *(const float4*)&X[(gj + 1) * DD + d0 + cl] : zero4;
        }

        // compute on current buffer
        {
            const float* base = sTop + ((g * 2 + cur) * 3) * ARR;
            const float* cXi = base;
            const float* cY0 = base + ARR;
            const float* cY1 = base + 2 * ARR;

            #pragma unroll
            for (int kk = 0; kk < BK; kk += 2) {
                float2 xi0 = *(const float2*)&cXi[(ty     ) * PAD + kk];
                float2 xi1 = *(const float2*)&cXi[(ty + 16) * PAD + kk];
                float2 a0  = *(const float2*)&cY0[(tx     ) * PAD + kk];
                float2 c0  = *(const float2*)&cY1[(tx     ) * PAD + kk];
                float2 a1  = *(const float2*)&cY0[(tx + 16) * PAD + kk];
                float2 c1  = *(const float2*)&cY1[(tx + 16) * PAD + kk];

                a000 += xi0.x * a0.x;  a000 += xi0.y * a0.y;
                a001 += xi0.x * c0.x;  a001 += xi0.y * c0.y;
                a010 += xi0.x * a1.x;  a010 += xi0.y * a1.y;
                a011 += xi0.x * c1.x;  a011 += xi0.y * c1.y;
                a100 += xi1.x * a0.x;  a100 += xi1.y * a0.y;
                a101 += xi1.x * c0.x;  a101 += xi1.y * c0.y;
                a110 += xi1.x * a1.x;  a110 += xi1.y * a1.y;
                a111 += xi1.x * c1.x;  a111 += xi1.y * c1.y;
            }
        }

        // write prefetched tile into the other buffer
        if (kt + 1 < KT_PER_G) {
            const int d0 = d_base + (kt + 1) * BK;
            STORE_TILE(1 - cur, d0);
        }
        GBAR();
    }

    // ---- cross-group reduction: group 1 -> smem, group 0 adds & stores ----
    __syncthreads();                    // everyone done with tile buffers
    float* sRed = sTop;                 // reuse: 256 threads x 8 floats
    if (g == 1) {
        float* p = &sRed[lt * 8];
        p[0] = a000; p[1] = a001; p[2] = a010; p[3] = a011;
        p[4] = a100; p[5] = a101; p[6] = a110; p[7] = a111;
    }
    __syncthreads();
    if (g == 0) {
        const float* p = &sRed[lt * 8];
        a000 += p[0]; a001 += p[1]; a010 += p[2]; a011 += p[3];
        a100 += p[4]; a101 += p[5]; a110 += p[6]; a111 += p[7];

        const float bb0 = b[0];
        const float bb1 = b[1];
        float2* out2 = (float2*)out;

        const int i0 = bi * TILE + ty;
        const int i1 = i0 + 16;
        const int j0 = bj * TILE + tx;
        const int j1 = j0 + 16;

        #define STORE_PAIR(I, J, A0, A1)                              \
            if ((I) < NN && (J) < NN) {                               \
                float2 v = make_float2((A0) + bb0, (A1) + bb1);       \
                out2[(I) * NN + (J)] = v;                             \
                out2[(J) * NN + (I)] = v;                             \
            }

        STORE_PAIR(i0, j0, a000, a001);
        STORE_PAIR(i0, j1, a010, a011);
        STORE_PAIR(i1, j0, a100, a101);
        STORE_PAIR(i1, j1, a110, a111);
        #undef STORE_PAIR
    }
}

extern "C" void kernel_launch(void* const* d_in, const int* in_sizes, int n_in,
                              void* d_out, int out_size)
{
    const float* X = (const float*)d_in[0];   // prev_result (1,512,1280)
    const float* W = (const float*)d_in[1];   // (2560,2)
    const float* b = (const float*)d_in[2];   // (2,)
    float* out = (float*)d_out;               // (510,510,2)

    const int smem_bytes = SMEM_FLOATS * (int)sizeof(float);
    cudaFuncSetAttribute(contact_gram_kernel,
                         cudaFuncAttributeMaxDynamicSharedMemorySize, smem_bytes);
    contact_gram_kernel<<<NBLK, THREADS, smem_bytes>>>(X, W, b, out);
}

// round 6
// speedup vs baseline: 1.9855x; 1.8107x over previous
#include <cuda_runtime.h>

// out[i,j,k] = sum_d X[i+1,d]*X[j+1,d]*Wp[d,k] + b[k]   (510,510,2) fp32
// Symmetric (diff term cancels). 64x64 triangular tiles (36), K-split 4
// -> 144 CTAs. Partials in __device__ scratch, reduce kernel adds bias.

#define DD   1280
#define NN   510
#define BT   64            // output tile
#define BK   16            // k-tile
#define NB   8             // 64*8 = 512 >= 510
#define NTILE 36           // NB*(NB+1)/2
#define KSPLIT 4
#define KLEN  (DD / KSPLIT)        // 320
#define KT    (KLEN / BK)          // 20
#define THREADS 256

__device__ float2 g_part[KSPLIT * NN * NN];   // 8.3 MB scratch (static)

__global__ __launch_bounds__(THREADS, 1)
void gram_partial_kernel(const float* __restrict__ X,
                         const float* __restrict__ W)
{
    // block -> (ks, triangular tile)
    const int blk = blockIdx.x;
    const int ks  = blk / NTILE;
    int rem = blk % NTILE, bi = 0;
    #pragma unroll
    for (int r = 0; r < NB; r++) { int len = NB - r; if (rem < len) { bi = r; break; } rem -= len; }
    const int bj = bi + rem;

    const int tid = threadIdx.x;
    const int tx  = tid & 15;
    const int ty  = tid >> 4;

    // smem: k-major layouts, double buffered
    __shared__ float2 sXi[2][BK / 2][BT];   // (k,k+1) for row i        : 8 KB
    __shared__ float4 sYj[2][BK / 2][BT];   // (k:w0,w1, k+1:w0,w1) * xj: 16 KB

    // fill mapping: r = row in tile, kq = which 4-d chunk
    const int r  = tid & 63;
    const int kq = tid >> 6;                // 0..3  (4*4 = 16 d per tile)
    const int gi = bi * BT + r;
    const int gj = bj * BT + r;
    const int d_base = ks * KLEN;

    const float4 z4 = make_float4(0.f, 0.f, 0.f, 0.f);
    float4 pxi, pxj, wA, wB;

    #define LOAD_REGS(d0)                                                     \
    {                                                                         \
        int d = (d0) + kq * 4;                                                \
        pxi = (gi < NN) ? *(const float4*)&X[(gi + 1) * DD + d] : z4;         \
        pxj = (gj < NN) ? *(const float4*)&X[(gj + 1) * DD + d] : z4;         \
        wA  = *(const float4*)&W[d * 2];      /* w0,w1 for d, d+1 */          \
        wB  = *(const float4*)&W[d * 2 + 4];  /* w0,w1 for d+2, d+3 */        \
    }

    #define STORE_SMEM(bf)                                                    \
    {                                                                         \
        sXi[bf][kq * 2    ][r] = make_float2(pxi.x, pxi.y);                   \
        sXi[bf][kq * 2 + 1][r] = make_float2(pxi.z, pxi.w);                   \
        sYj[bf][kq * 2    ][r] = make_float4(pxj.x * wA.x, pxj.x * wA.y,      \
                                             pxj.y * wA.z, pxj.y * wA.w);     \
        sYj[bf][kq * 2 + 1][r] = make_float4(pxj.z * wB.x, pxj.z * wB.y,      \
                                             pxj.w * wB.z, pxj.w * wB.w);     \
    }

    LOAD_REGS(d_base);
    STORE_SMEM(0);
    __syncthreads();

    float2 acc[4][4];
    #pragma unroll
    for (int m = 0; m < 4; m++)
        #pragma unroll
        for (int n = 0; n < 4; n++) acc[m][n] = make_float2(0.f, 0.f);

    for (int kt = 0; kt < KT; kt++) {
        const int cur = kt & 1;

        if (kt + 1 < KT) LOAD_REGS(d_base + (kt + 1) * BK);

        #pragma unroll
        for (int kp = 0; kp < BK / 2; kp++) {
            float2 xi[4];
            float4 yj[4];
            #pragma unroll
            for (int m = 0; m < 4; m++) xi[m] = sXi[cur][kp][ty + 16 * m];
            #pragma unroll
            for (int n = 0; n < 4; n++) yj[n] = sYj[cur][kp][tx + 16 * n];

            #pragma unroll
            for (int m = 0; m < 4; m++)
                #pragma unroll
                for (int n = 0; n < 4; n++) {
                    acc[m][n].x += xi[m].x * yj[n].x;
                    acc[m][n].x += xi[m].y * yj[n].z;
                    acc[m][n].y += xi[m].x * yj[n].y;
                    acc[m][n].y += xi[m].y * yj[n].w;
                }
        }

        if (kt + 1 < KT) STORE_SMEM(1 - cur);
        __syncthreads();
    }

    // write partials (mirrored: output is symmetric)
    float2* part = g_part + (size_t)ks * (NN * NN);
    #pragma unroll
    for (int m = 0; m < 4; m++) {
        const int i = bi * BT + ty + 16 * m;
        if (i >= NN) continue;
        #pragma unroll
        for (int n = 0; n < 4; n++) {
            const int j = bj * BT + tx + 16 * n;
            if (j >= NN) continue;
            part[i * NN + j] = acc[m][n];
            part[j * NN + i] = acc[m][n];
        }
    }
    #undef LOAD_REGS
    #undef STORE_SMEM
}

__global__ __launch_bounds__(512)
void reduce_bias_kernel(const float* __restrict__ b, float2* __restrict__ out)
{
    const int idx = blockIdx.x * blockDim.x + threadIdx.x;
    if (idx >= NN * NN) return;
    float2 s0 = g_part[idx];
    float2 s1 = g_part[NN * NN + idx];
    float2 s2 = g_part[2 * NN * NN + idx];
    float2 s3 = g_part[3 * NN * NN + idx];
    out[idx] = make_float2(s0.x + s1.x + s2.x + s3.x + b[0],
                           s0.y + s1.y + s2.y + s3.y + b[1]);
}

extern "C" void kernel_launch(void* const* d_in, const int* in_sizes, int n_in,
                              void* d_out, int out_size)
{
    const float* X = (const float*)d_in[0];   // (1,512,1280)
    const float* W = (const float*)d_in[1];   // (2560,2)
    const float* b = (const float*)d_in[2];   // (2,)
    float2* out = (float2*)d_out;             // (510,510,2) -> float2 per (i,j)

    gram_partial_kernel<<<KSPLIT * NTILE, THREADS>>>(X, W);
    reduce_bias_kernel<<<(NN * NN + 511) / 512, 512>>>(b, out);
}

// round 7
// speedup vs baseline: 2.0956x; 1.0554x over previous
#include <cuda_runtime.h>

// out[i,j,k] = sum_d X[i+1,d]*X[j+1,d]*Wp[d,k] + b[k]   (510,510,2) fp32
// Symmetric (diff term cancels). 64x64 triangular tiles (36), K-split 8
// -> 288 CTAs, 2 CTAs/SM resident. Partials in __device__ scratch,
// vectorized reduce kernel adds bias.

#define DD   1280
#define NN   510
#define BT   64            // output tile
#define BK   16            // k-tile
#define NB   8             // 64*8 = 512 >= 510
#define NTILE 36           // NB*(NB+1)/2
#define KSPLIT 8
#define KLEN  (DD / KSPLIT)        // 160
#define KT    (KLEN / BK)          // 10
#define THREADS 256

__device__ float2 g_part[KSPLIT * NN * NN];   // 16.6 MB scratch (static)

__global__ __launch_bounds__(THREADS, 2)
void gram_partial_kernel(const float* __restrict__ X,
                         const float* __restrict__ W)
{
    // block -> (ks, triangular tile)
    const int blk = blockIdx.x;
    const int ks  = blk / NTILE;
    int rem = blk % NTILE, bi = 0;
    #pragma unroll
    for (int r = 0; r < NB; r++) { int len = NB - r; if (rem < len) { bi = r; break; } rem -= len; }
    const int bj = bi + rem;

    const int tid = threadIdx.x;
    const int tx  = tid & 15;
    const int ty  = tid >> 4;

    // smem: k-major layouts, double buffered
    __shared__ float2 sXi[2][BK / 2][BT];   // (k,k+1) for row i        : 8 KB
    __shared__ float4 sYj[2][BK / 2][BT];   // (k:w0,w1, k+1:w0,w1) * xj: 16 KB

    // fill mapping: r = row in tile, kq = which 4-d chunk
    const int r  = tid & 63;
    const int kq = tid >> 6;                // 0..3  (4*4 = 16 d per tile)
    const int gi = bi * BT + r;
    const int gj = bj * BT + r;
    const int d_base = ks * KLEN;

    const float4 z4 = make_float4(0.f, 0.f, 0.f, 0.f);
    float4 pxi, pxj, wA, wB;

    #define LOAD_REGS(d0)                                                     \
    {                                                                         \
        int d = (d0) + kq * 4;                                                \
        pxi = (gi < NN) ? *(const float4*)&X[(gi + 1) * DD + d] : z4;         \
        pxj = (gj < NN) ? *(const float4*)&X[(gj + 1) * DD + d] : z4;         \
        wA  = *(const float4*)&W[d * 2];      /* w0,w1 for d, d+1 */          \
        wB  = *(const float4*)&W[d * 2 + 4];  /* w0,w1 for d+2, d+3 */        \
    }

    #define STORE_SMEM(bf)                                                    \
    {                                                                         \
        sXi[bf][kq * 2    ][r] = make_float2(pxi.x, pxi.y);                   \
        sXi[bf][kq * 2 + 1][r] = make_float2(pxi.z, pxi.w);                   \
        sYj[bf][kq * 2    ][r] = make_float4(pxj.x * wA.x, pxj.x * wA.y,      \
                                             pxj.y * wA.z, pxj.y * wA.w);     \
        sYj[bf][kq * 2 + 1][r] = make_float4(pxj.z * wB.x, pxj.z * wB.y,      \
                                             pxj.w * wB.z, pxj.w * wB.w);     \
    }

    LOAD_REGS(d_base);
    STORE_SMEM(0);
    __syncthreads();

    float2 acc[4][4];
    #pragma unroll
    for (int m = 0; m < 4; m++)
        #pragma unroll
        for (int n = 0; n < 4; n++) acc[m][n] = make_float2(0.f, 0.f);

    for (int kt = 0; kt < KT; kt++) {
        const int cur = kt & 1;

        if (kt + 1 < KT) LOAD_REGS(d_base + (kt + 1) * BK);

        #pragma unroll
        for (int kp = 0; kp < BK / 2; kp++) {
            float2 xi[4];
            float4 yj[4];
            #pragma unroll
            for (int m = 0; m < 4; m++) xi[m] = sXi[cur][kp][ty + 16 * m];
            #pragma unroll
            for (int n = 0; n < 4; n++) yj[n] = sYj[cur][kp][tx + 16 * n];

            #pragma unroll
            for (int m = 0; m < 4; m++)
                #pragma unroll
                for (int n = 0; n < 4; n++) {
                    acc[m][n].x += xi[m].x * yj[n].x;
                    acc[m][n].x += xi[m].y * yj[n].z;
                    acc[m][n].y += xi[m].x * yj[n].y;
                    acc[m][n].y += xi[m].y * yj[n].w;
                }
        }

        if (kt + 1 < KT) STORE_SMEM(1 - cur);
        __syncthreads();
    }

    // write partials (mirrored: output is symmetric)
    float2* part = g_part + (size_t)ks * (NN * NN);
    #pragma unroll
    for (int m = 0; m < 4; m++) {
        const int i = bi * BT + ty + 16 * m;
        if (i >= NN) continue;
        #pragma unroll
        for (int n = 0; n < 4; n++) {
            const int j = bj * BT + tx + 16 * n;
            if (j >= NN) continue;
            part[i * NN + j] = acc[m][n];
            part[j * NN + i] = acc[m][n];
        }
    }
    #undef LOAD_REGS
    #undef STORE_SMEM
}

// N4 = number of float4 elements in one partial plane (and in out)
#define N4 ((NN * NN * 2) / 4)     // 130050 exactly

__global__ __launch_bounds__(256)
void reduce_bias_kernel(const float* __restrict__ b, float4* __restrict__ out)
{
    const int idx = blockIdx.x * blockDim.x + threadIdx.x;
    if (idx >= N4) return;

    const float4* p = (const float4*)g_part;

    // 8 independent loads (MLP=8), all L2-resident
    float4 v0 = p[0 * N4 + idx];
    float4 v1 = p[1 * N4 + idx];
    float4 v2 = p[2 * N4 + idx];
    float4 v3 = p[3 * N4 + idx];
    float4 v4 = p[4 * N4 + idx];
    float4 v5 = p[5 * N4 + idx];
    float4 v6 = p[6 * N4 + idx];
    float4 v7 = p[7 * N4 + idx];

    const float b0 = b[0];
    const float b1 = b[1];

    float4 s;
    s.x = ((v0.x + v1.x) + (v2.x + v3.x)) + ((v4.x + v5.x) + (v6.x + v7.x)) + b0;
    s.y = ((v0.y + v1.y) + (v2.y + v3.y)) + ((v4.y + v5.y) + (v6.y + v7.y)) + b1;
    s.z = ((v0.z + v1.z) + (v2.z + v3.z)) + ((v4.z + v5.z) + (v6.z + v7.z)) + b0;
    s.w = ((v0.w + v1.w) + (v2.w + v3.w)) + ((v4.w + v5.w) + (v6.w + v7.w)) + b1;
    out[idx] = s;
}

extern "C" void kernel_launch(void* const* d_in, const int* in_sizes, int n_in,
                              void* d_out, int out_size)
{
    const float* X = (const float*)d_in[0];   // (1,512,1280)
    const float* W = (const float*)d_in[1];   // (2560,2)
    const float* b = (const float*)d_in[2];   // (2,)
    float4* out = (float4*)d_out;             // (510,510,2) fp32

    gram_partial_kernel<<<KSPLIT * NTILE, THREADS>>>(X, W);
    reduce_bias_kernel<<<(N4 + 255) / 256, 256>>>(b, out);
}

// round 14
// speedup vs baseline: 2.4035x; 1.1469x over previous
#include <cuda_runtime.h>
#include <cuda_bf16.h>
#include <cstdint>

// out[i,j,k] = sum_d X[i+1,d]*X[j+1,d]*W[d,k] + b[k]  -> (510,510,2) fp32
// bf16 split-3 via legacy tensor path (mma.sync m16n8k16, sm_80+ features only;
// tcgen05 is rejected by this toolchain's .target sm_103).
// C ~= Xh Yh^T + Xh Yl^T + Xl Yh^T, fp32 accumulate.
// Full 8x8 grid of 64x64 tiles x 2 channels = 128 CTAs, K=1280 per CTA.

#define DD 1280
#define NN 510
#define BT 64            // CTA tile (M=N=64)
#define KC 32            // k-chunk per stage
#define NS (DD / KC)     // 40 stages
#define THREADS 256
#define SROW 80          // smem row stride in bytes (32 bf16 + 16B pad)
#define ARRB (64 * SROW) // 5120 B per operand array

__device__ __align__(16) __nv_bfloat16 g_xh[512 * DD];
__device__ __align__(16) __nv_bfloat16 g_xl[512 * DD];
__device__ __align__(16) __nv_bfloat16 g_y0h[512 * DD];
__device__ __align__(16) __nv_bfloat16 g_y0l[512 * DD];
__device__ __align__(16) __nv_bfloat16 g_y1h[512 * DD];
__device__ __align__(16) __nv_bfloat16 g_y1l[512 * DD];

// ---------------- split kernel: fp32 -> (hi, lo) bf16 planes ----------------
__global__ __launch_bounds__(256)
void split_kernel(const float* __restrict__ X, const float* __restrict__ W)
{
    int idx = blockIdx.x * 256 + threadIdx.x;
    if (idx >= 512 * (DD / 4)) return;
    int i  = idx / (DD / 4);
    int dq = (idx % (DD / 4)) * 4;

    float4 x = make_float4(0.f, 0.f, 0.f, 0.f);
    if (i < 511) x = *(const float4*)&X[(i + 1) * DD + dq];   // shifted row
    float4 wa = *(const float4*)&W[dq * 2];
    float4 wb = *(const float4*)&W[dq * 2 + 4];

    float xx[4] = {x.x, x.y, x.z, x.w};
    float w0[4] = {wa.x, wa.z, wb.x, wb.z};
    float w1[4] = {wa.y, wa.w, wb.y, wb.w};

    __align__(8) __nv_bfloat16 xh[4], xl[4], y0h[4], y0l[4], y1h[4], y1l[4];
    #pragma unroll
    for (int q = 0; q < 4; q++) {
        float v = xx[q];
        __nv_bfloat16 h = __float2bfloat16_rn(v);
        xh[q] = h; xl[q] = __float2bfloat16_rn(v - __bfloat162float(h));
        float y0 = v * w0[q];
        h = __float2bfloat16_rn(y0);
        y0h[q] = h; y0l[q] = __float2bfloat16_rn(y0 - __bfloat162float(h));
        float y1 = v * w1[q];
        h = __float2bfloat16_rn(y1);
        y1h[q] = h; y1l[q] = __float2bfloat16_rn(y1 - __bfloat162float(h));
    }
    size_t off = (size_t)i * DD + dq;
    *(uint2*)&g_xh[off]  = *(uint2*)xh;
    *(uint2*)&g_xl[off]  = *(uint2*)xl;
    *(uint2*)&g_y0h[off] = *(uint2*)y0h;
    *(uint2*)&g_y0l[off] = *(uint2*)y0l;
    *(uint2*)&g_y1h[off] = *(uint2*)y1h;
    *(uint2*)&g_y1l[off] = *(uint2*)y1l;
}

// ---------------- helpers ----------------
static __device__ __forceinline__ uint32_t smem_u32(const void* p) {
    uint32_t a;
    asm("{ .reg .u64 t; cvta.to.shared.u64 t, %1; cvt.u32.u64 %0, t; }"
        : "=r"(a) : "l"(p));
    return a;
}

#define CP_ASYNC16(saddr, gptr) \
    asm volatile("cp.async.cg.shared.global [%0], [%1], 16;" \
                 :: "r"(saddr), "l"(gptr) : "memory")
#define CP_COMMIT() asm volatile("cp.async.commit_group;" ::: "memory")
#define CP_WAIT1()  asm volatile("cp.async.wait_group 1;" ::: "memory")
#define CP_WAIT0()  asm volatile("cp.async.wait_group 0;" ::: "memory")

#define LDSM4(r, addr) \
    asm volatile("ldmatrix.sync.aligned.m8n8.x4.shared.b16 {%0,%1,%2,%3}, [%4];" \
                 : "=r"((r)[0]), "=r"((r)[1]), "=r"((r)[2]), "=r"((r)[3]) \
                 : "r"(addr))

#define MMA(ac, af, b0v, b1v) \
    asm volatile("mma.sync.aligned.m16n8k16.row.col.f32.bf16.bf16.f32 " \
                 "{%0,%1,%2,%3}, {%4,%5,%6,%7}, {%8,%9}, {%0,%1,%2,%3};" \
                 : "+f"((ac)[0]), "+f"((ac)[1]), "+f"((ac)[2]), "+f"((ac)[3]) \
                 : "r"((af)[0]), "r"((af)[1]), "r"((af)[2]), "r"((af)[3]), \
                   "r"(b0v), "r"(b1v))

// ---------------- GEMM kernel ----------------
__global__ __launch_bounds__(THREADS, 1)
void gram_mma_kernel(const float* __restrict__ b, float* __restrict__ out)
{
    // smem: [stage 0/1][Ah, Al, Bh, Bl][64 rows x 80B]
    __shared__ __align__(16) char smem[2][4][ARRB];
    const uint32_t sb = smem_u32(smem);

    const int tid  = threadIdx.x;
    const int lane = tid & 31;
    const int w    = tid >> 5;
    const int wm   = w >> 2;           // 0..1
    const int wn   = w & 3;            // 0..3
    const int m_base = wm * 32;
    const int n_base = wn * 16;

    const int bid = blockIdx.x;
    const int ch  = bid >> 6;
    const int t6  = bid & 63;
    const int i0  = (t6 >> 3) * BT;
    const int j0  = (t6 & 7) * BT;

    const __nv_bfloat16* Ahp = g_xh;
    const __nv_bfloat16* Alp = g_xl;
    const __nv_bfloat16* Bhp = ch ? g_y1h : g_y0h;
    const __nv_bfloat16* Blp = ch ? g_y1l : g_y0l;

    // cp.async fill mapping: thread -> (row, 16B segment), one per array
    const int frow = tid >> 2;         // 0..63
    const int fs   = tid & 3;          // 0..3
    const uint32_t dstOff = (uint32_t)frow * SROW + fs * 16;
    const size_t gA = ((size_t)(i0 + frow) * DD) + fs * 8;   // + k0 elems
    const size_t gB = ((size_t)(j0 + frow) * DD) + fs * 8;

    #define FILL(c, buf)                                                     \
    {                                                                        \
        const int k0 = (c) * KC;                                             \
        CP_ASYNC16(sb + ((buf) * 4 + 0) * ARRB + dstOff, Ahp + gA + k0);     \
        CP_ASYNC16(sb + ((buf) * 4 + 1) * ARRB + dstOff, Alp + gA + k0);     \
        CP_ASYNC16(sb + ((buf) * 4 + 2) * ARRB + dstOff, Bhp + gB + k0);     \
        CP_ASYNC16(sb + ((buf) * 4 + 3) * ARRB + dstOff, Blp + gB + k0);     \
        CP_COMMIT();                                                         \
    }

    // ldmatrix per-lane offsets (within a 64x80B operand array)
    // A (row-major MxK): mats m0k0, m8k0, m0k8, m8k8
    const int aRow = (lane & 7) + ((lane >> 3) & 1) * 8;
    const int aK   = (lane >> 4) * 8;
    // B (N-major NxK): mats n0k0, n0k8, n8k0, n8k8  -> regs {b0n0,b1n0,b0n1,b1n1}
    const int bRow = (lane & 7) + (lane >> 4) * 8;
    const int bK   = ((lane >> 3) & 1) * 8;

    const uint32_t aOff0 = (uint32_t)(m_base + aRow) * SROW + aK * 2;       // mt=0
    const uint32_t aOff1 = aOff0 + 16 * SROW;                               // mt=1
    const uint32_t bOff  = (uint32_t)(n_base + bRow) * SROW + bK * 2;

    float acc[2][2][4];
    #pragma unroll
    for (int mt = 0; mt < 2; mt++)
        #pragma unroll
        for (int nt = 0; nt < 2; nt++)
            #pragma unroll
            for (int e = 0; e < 4; e++) acc[mt][nt][e] = 0.f;

    FILL(0, 0);

    for (int c = 0; c < NS; c++) {
        const int buf = c & 1;
        if (c + 1 < NS) {
            FILL(c + 1, (c + 1) & 1);
            CP_WAIT1();
        } else {
            CP_WAIT0();
        }
        __syncthreads();

        const uint32_t sAh = sb + (buf * 4 + 0) * ARRB;
        const uint32_t sAl = sb + (buf * 4 + 1) * ARRB;
        const uint32_t sBh = sb + (buf * 4 + 2) * ARRB;
        const uint32_t sBl = sb + (buf * 4 + 3) * ARRB;

        #pragma unroll
        for (int kk = 0; kk < KC; kk += 16) {
            uint32_t ah[2][4], al[2][4], bh[4], bl[4];
            LDSM4(ah[0], sAh + aOff0 + kk * 2);
            LDSM4(ah[1], sAh + aOff1 + kk * 2);
            LDSM4(al[0], sAl + aOff0 + kk * 2);
            LDSM4(al[1], sAl + aOff1 + kk * 2);
            LDSM4(bh,    sBh + bOff  + kk * 2);
            LDSM4(bl,    sBl + bOff  + kk * 2);

            #pragma unroll
            for (int mt = 0; mt < 2; mt++)
                #pragma unroll
                for (int nt = 0; nt < 2; nt++) {
                    MMA(acc[mt][nt], ah[mt], bh[2 * nt], bh[2 * nt + 1]);
                    MMA(acc[mt][nt], ah[mt], bl[2 * nt], bl[2 * nt + 1]);
                    MMA(acc[mt][nt], al[mt], bh[2 * nt], bh[2 * nt + 1]);
                }
        }
        __syncthreads();
    }

    // epilogue: C frag c0=C[g][2t] c1=C[g][2t+1] c2=C[g+8][2t] c3=C[g+8][2t+1]
    const float bias = __ldg(&b[ch]);
    const int g = lane >> 2;
    const int t = lane & 3;

    #pragma unroll
    for (int mt = 0; mt < 2; mt++) {
        #pragma unroll
        for (int nt = 0; nt < 2; nt++) {
            const int i = i0 + m_base + mt * 16 + g;
            const int j = j0 + n_base + nt * 8 + 2 * t;
            const float* a = acc[mt][nt];
            if (i < NN) {
                if (j     < NN) out[((size_t)i * NN + j)     * 2 + ch] = a[0] + bias;
                if (j + 1 < NN) out[((size_t)i * NN + j + 1) * 2 + ch] = a[1] + bias;
            }
            if (i + 8 < NN) {
                if (j     < NN) out[((size_t)(i + 8) * NN + j)     * 2 + ch] = a[2] + bias;
                if (j + 1 < NN) out[((size_t)(i + 8) * NN + j + 1) * 2 + ch] = a[3] + bias;
            }
        }
    }
    #undef FILL
}

extern "C" void kernel_launch(void* const* d_in, const int* in_sizes, int n_in,
                              void* d_out, int out_size)
{
    const float* X = (const float*)d_in[0];   // (1,512,1280)
    const float* W = (const float*)d_in[1];   // (2560,2)
    const float* b = (const float*)d_in[2];   // (2,)
    float* out = (float*)d_out;               // (510,510,2)

    split_kernel<<<(512 * (DD / 4) + 255) / 256, 256>>>(X, W);
    gram_mma_kernel<<<128, THREADS>>>(b, out);
}